// round 1
// baseline (speedup 1.0000x reference)
#include <cuda_runtime.h>
#include <math.h>

// ---------------- scratch (device globals; no cudaMalloc allowed) ----------------
// g_Y: conv1x1 outputs  [2][8][256][1024]
// g_F: conv3x3 outputs (pre-BN, then normalized in place) [2][8][512][1024]
// g_S: attention scores [8][512][512]
__device__ float g_Y[2 * 8 * 256 * 1024];
__device__ float g_F[2 * 8 * 512 * 1024];
__device__ float g_S[8 * 512 * 512];
// per-block BN partials: [t*512+co][64 blocks]  (b(8) x rowquad(8))
__device__ float g_psum[1024 * 64];
__device__ float g_psumq[1024 * 64];
__device__ float g_bn_a[1024];
__device__ float g_bn_c[1024];

#define LRELU 0.01f
#define BN_EPS 1e-5f

// ---------------- conv 1x1 : Y[256x1024] = W1[256x512] * X[512x1024] + b1 ----------
__global__ __launch_bounds__(256) void conv1x1_kernel(
    const float* __restrict__ x1, const float* __restrict__ x2,
    const float* __restrict__ w1, const float* __restrict__ b1)
{
    int z = blockIdx.z;            // t*8 + b
    int t = z >> 3;
    const float* X = (t ? x2 : x1) + (size_t)(z & 7) * 512 * 1024;
    float* Y = g_Y + (size_t)z * 256 * 1024;

    int m0 = blockIdx.y * 64, n0 = blockIdx.x * 64;
    __shared__ float sA[16][65];
    __shared__ __align__(16) float sB[16][64];

    int tid = threadIdx.x;
    int ty = tid >> 4, tx = tid & 15;
    float acc[4][4] = {};

    for (int k0 = 0; k0 < 512; k0 += 16) {
        #pragma unroll
        for (int i = 0; i < 4; i++) {
            int idx = tid + i * 256;
            int m = idx >> 4, k = idx & 15;
            sA[k][m] = w1[(size_t)(m0 + m) * 512 + k0 + k];
        }
        #pragma unroll
        for (int i = 0; i < 4; i++) {
            int idx = tid + i * 256;
            int k = idx >> 6, n = idx & 63;
            sB[k][n] = X[(size_t)(k0 + k) * 1024 + n0 + n];
        }
        __syncthreads();
        #pragma unroll
        for (int k = 0; k < 16; k++) {
            float a0 = sA[k][ty * 4 + 0];
            float a1 = sA[k][ty * 4 + 1];
            float a2 = sA[k][ty * 4 + 2];
            float a3 = sA[k][ty * 4 + 3];
            float4 bb = *(const float4*)&sB[k][tx * 4];
            acc[0][0] += a0 * bb.x; acc[0][1] += a0 * bb.y; acc[0][2] += a0 * bb.z; acc[0][3] += a0 * bb.w;
            acc[1][0] += a1 * bb.x; acc[1][1] += a1 * bb.y; acc[1][2] += a1 * bb.z; acc[1][3] += a1 * bb.w;
            acc[2][0] += a2 * bb.x; acc[2][1] += a2 * bb.y; acc[2][2] += a2 * bb.z; acc[2][3] += a2 * bb.w;
            acc[3][0] += a3 * bb.x; acc[3][1] += a3 * bb.y; acc[3][2] += a3 * bb.z; acc[3][3] += a3 * bb.w;
        }
        __syncthreads();
    }
    #pragma unroll
    for (int i = 0; i < 4; i++) {
        float bias = b1[m0 + ty * 4 + i];
        #pragma unroll
        for (int j = 0; j < 4; j++)
            Y[(size_t)(m0 + ty * 4 + i) * 1024 + n0 + tx * 4 + j] = acc[i][j] + bias;
    }
}

// ---------------- conv 3x3 (SAME) + bias + LeakyReLU + BN partial sums -------------
// Block: 32 out-channels x 4 rows x 32 cols. 256 threads: g=tid&31 (col), cg=tid>>5.
__global__ __launch_bounds__(256) void conv3x3_kernel(
    const float* __restrict__ w2, const float* __restrict__ b2)
{
    int z  = blockIdx.z;           // t*8 + b
    int t  = z >> 3;
    int co0 = blockIdx.y * 32;
    int h0  = blockIdx.x * 4;
    const float* Y = g_Y + (size_t)z * 256 * 1024;
    float* F = g_F + (size_t)z * 512 * 1024;

    __shared__ float sY[16][6][34];  // ci x rows(h0-1..h0+4) x cols(-1..32)
    __shared__ float sW[16][9][33];  // ci x tap x co (padded)

    int tid = threadIdx.x;
    int g = tid & 31, cg = tid >> 5;

    float acc[4][4] = {};  // [j=co][r=row]

    for (int ci0 = 0; ci0 < 256; ci0 += 16) {
        for (int idx = tid; idx < 16 * 6 * 34; idx += 256) {
            int ci = idx / 204;
            int rem = idx - ci * 204;
            int r = rem / 34;
            int c = rem - r * 34;
            int gh = h0 - 1 + r;
            int gw = c - 1;
            float v = 0.f;
            if ((unsigned)gh < 32u && (unsigned)gw < 32u)
                v = Y[(size_t)(ci0 + ci) * 1024 + gh * 32 + gw];
            sY[ci][r][c] = v;
        }
        for (int idx = tid; idx < 16 * 9 * 32; idx += 256) {
            int co = idx / 144;
            int rem = idx - co * 144;
            int ci = rem / 9;
            int tap = rem - ci * 9;
            sW[ci][tap][co] = w2[(size_t)(co0 + co) * 2304 + (ci0 + ci) * 9 + tap];
        }
        __syncthreads();

        #pragma unroll 4
        for (int ci = 0; ci < 16; ci++) {
            #pragma unroll
            for (int tap = 0; tap < 9; tap++) {
                const int dh = tap / 3, dw = tap % 3;
                float w0 = sW[ci][tap][cg * 4 + 0];
                float w1v = sW[ci][tap][cg * 4 + 1];
                float w2v = sW[ci][tap][cg * 4 + 2];
                float w3v = sW[ci][tap][cg * 4 + 3];
                #pragma unroll
                for (int r = 0; r < 4; r++) {
                    float yv = sY[ci][r + dh][g + dw];
                    acc[0][r] += w0  * yv;
                    acc[1][r] += w1v * yv;
                    acc[2][r] += w2v * yv;
                    acc[3][r] += w3v * yv;
                }
            }
        }
        __syncthreads();
    }

    // epilogue: bias, leaky relu, store, per-channel block partial sums (deterministic)
    int blk = (z & 7) * 8 + blockIdx.x;  // 0..63 within (t,co)
    #pragma unroll
    for (int j = 0; j < 4; j++) {
        int co = co0 + cg * 4 + j;
        float bias = b2[co];
        float s = 0.f, q = 0.f;
        #pragma unroll
        for (int r = 0; r < 4; r++) {
            float v = acc[j][r] + bias;
            v = v > 0.f ? v : LRELU * v;
            F[(size_t)co * 1024 + (h0 + r) * 32 + g] = v;
            s += v;
            q += v * v;
        }
        #pragma unroll
        for (int o = 16; o > 0; o >>= 1) {
            s += __shfl_xor_sync(0xffffffffu, s, o);
            q += __shfl_xor_sync(0xffffffffu, q, o);
        }
        if (g == 0) {
            g_psum [(size_t)(t * 512 + co) * 64 + blk] = s;
            g_psumq[(size_t)(t * 512 + co) * 64 + blk] = q;
        }
    }
}

// ---------------- BN stats: fixed-order reduction over 64 partials ----------------
__global__ void bn_stats_kernel(const float* __restrict__ gamma,
                                const float* __restrict__ bn_bias)
{
    int i = blockIdx.x * blockDim.x + threadIdx.x;  // 0..1023 = t*512+co
    if (i >= 1024) return;
    float s = 0.f, q = 0.f;
    #pragma unroll 8
    for (int p = 0; p < 64; p++) {
        s += g_psum [(size_t)i * 64 + p];
        q += g_psumq[(size_t)i * 64 + p];
    }
    const float inv_n = 1.0f / 8192.0f;
    float mean = s * inv_n;
    float var = q * inv_n - mean * mean;
    float a = gamma[i & 511] * rsqrtf(var + BN_EPS);
    g_bn_a[i] = a;
    g_bn_c[i] = bn_bias[i & 511] - mean * a;
}

// ---------------- BN apply in place -----------------------------------------------
__global__ void bn_apply_kernel()
{
    int idx = blockIdx.x * 256 + threadIdx.x;   // 0 .. 2*8*512*1024-1
    int ch = (idx >> 10) & 511;
    int t = idx >> 22;
    float v = g_F[idx];
    g_F[idx] = v * g_bn_a[t * 512 + ch] + g_bn_c[t * 512 + ch];
}

// ---------------- scores: S[b] = F1[b] * F2[b]^T  (512x512, K=1024) ----------------
__global__ __launch_bounds__(256) void scores_kernel()
{
    int b = blockIdx.z;
    const float* A = g_F + (size_t)b * 512 * 1024;            // t=0
    const float* B = g_F + (size_t)(8 + b) * 512 * 1024;      // t=1
    float* S = g_S + (size_t)b * 512 * 512;

    int m0 = blockIdx.y * 64, n0 = blockIdx.x * 64;
    __shared__ float sA[16][65];
    __shared__ float sB[16][65];

    int tid = threadIdx.x;
    int ty = tid >> 4, tx = tid & 15;
    float acc[4][4] = {};

    for (int k0 = 0; k0 < 1024; k0 += 16) {
        #pragma unroll
        for (int i = 0; i < 4; i++) {
            int idx = tid + i * 256;
            int m = idx >> 4, k = idx & 15;
            sA[k][m] = A[(size_t)(m0 + m) * 1024 + k0 + k];
            sB[k][m] = B[(size_t)(n0 + m) * 1024 + k0 + k];
        }
        __syncthreads();
        #pragma unroll
        for (int k = 0; k < 16; k++) {
            float a0 = sA[k][ty * 4 + 0], a1 = sA[k][ty * 4 + 1];
            float a2 = sA[k][ty * 4 + 2], a3 = sA[k][ty * 4 + 3];
            float b0 = sB[k][tx * 4 + 0], b1 = sB[k][tx * 4 + 1];
            float b2 = sB[k][tx * 4 + 2], b3 = sB[k][tx * 4 + 3];
            acc[0][0] += a0 * b0; acc[0][1] += a0 * b1; acc[0][2] += a0 * b2; acc[0][3] += a0 * b3;
            acc[1][0] += a1 * b0; acc[1][1] += a1 * b1; acc[1][2] += a1 * b2; acc[1][3] += a1 * b3;
            acc[2][0] += a2 * b0; acc[2][1] += a2 * b1; acc[2][2] += a2 * b2; acc[2][3] += a2 * b3;
            acc[3][0] += a3 * b0; acc[3][1] += a3 * b1; acc[3][2] += a3 * b2; acc[3][3] += a3 * b3;
        }
        __syncthreads();
    }
    #pragma unroll
    for (int i = 0; i < 4; i++)
        #pragma unroll
        for (int j = 0; j < 4; j++)
            S[(size_t)(m0 + ty * 4 + i) * 512 + n0 + tx * 4 + j] = acc[i][j];
}

// ---------------- softmax over last dim (512) of g_S -------------------------------
__global__ void softmax_kernel()
{
    int row = blockIdx.x;                      // b*512 + c
    float* s = g_S + (size_t)row * 512;
    int tid = threadIdx.x;                     // 256

    float v0 = s[tid], v1 = s[tid + 256];
    float m = fmaxf(v0, v1);
    __shared__ float red[8];
    #pragma unroll
    for (int o = 16; o > 0; o >>= 1)
        m = fmaxf(m, __shfl_xor_sync(0xffffffffu, m, o));
    if ((tid & 31) == 0) red[tid >> 5] = m;
    __syncthreads();
    float M = fmaxf(fmaxf(fmaxf(red[0], red[1]), fmaxf(red[2], red[3])),
                    fmaxf(fmaxf(red[4], red[5]), fmaxf(red[6], red[7])));
    __syncthreads();

    float e0 = expf(v0 - M), e1 = expf(v1 - M);
    float sum = e0 + e1;
    #pragma unroll
    for (int o = 16; o > 0; o >>= 1)
        sum += __shfl_xor_sync(0xffffffffu, sum, o);
    if ((tid & 31) == 0) red[tid >> 5] = sum;
    __syncthreads();
    float T = red[0] + red[1] + red[2] + red[3] + red[4] + red[5] + red[6] + red[7];
    float inv = 1.0f / T;
    s[tid] = e0 * inv;
    s[tid + 256] = e1 * inv;
}

// ---------------- out: O[b] = beta * (Attn[b] * X[b])  (512x1024, K=512) -----------
__global__ __launch_bounds__(256) void out_kernel(
    const float* __restrict__ x, const float* __restrict__ beta,
    float* __restrict__ out)
{
    int b = blockIdx.z;
    const float* A = g_S + (size_t)b * 512 * 512;
    const float* X = x + (size_t)b * 512 * 1024;
    float* O = out + (size_t)b * 512 * 1024;

    int m0 = blockIdx.y * 64, n0 = blockIdx.x * 64;
    __shared__ float sA[16][65];
    __shared__ __align__(16) float sB[16][64];

    int tid = threadIdx.x;
    int ty = tid >> 4, tx = tid & 15;
    float acc[4][4] = {};

    for (int k0 = 0; k0 < 512; k0 += 16) {
        #pragma unroll
        for (int i = 0; i < 4; i++) {
            int idx = tid + i * 256;
            int m = idx >> 4, k = idx & 15;
            sA[k][m] = A[(size_t)(m0 + m) * 512 + k0 + k];
        }
        #pragma unroll
        for (int i = 0; i < 4; i++) {
            int idx = tid + i * 256;
            int k = idx >> 6, n = idx & 63;
            sB[k][n] = X[(size_t)(k0 + k) * 1024 + n0 + n];
        }
        __syncthreads();
        #pragma unroll
        for (int k = 0; k < 16; k++) {
            float a0 = sA[k][ty * 4 + 0];
            float a1 = sA[k][ty * 4 + 1];
            float a2 = sA[k][ty * 4 + 2];
            float a3 = sA[k][ty * 4 + 3];
            float4 bb = *(const float4*)&sB[k][tx * 4];
            acc[0][0] += a0 * bb.x; acc[0][1] += a0 * bb.y; acc[0][2] += a0 * bb.z; acc[0][3] += a0 * bb.w;
            acc[1][0] += a1 * bb.x; acc[1][1] += a1 * bb.y; acc[1][2] += a1 * bb.z; acc[1][3] += a1 * bb.w;
            acc[2][0] += a2 * bb.x; acc[2][1] += a2 * bb.y; acc[2][2] += a2 * bb.z; acc[2][3] += a2 * bb.w;
            acc[3][0] += a3 * bb.x; acc[3][1] += a3 * bb.y; acc[3][2] += a3 * bb.z; acc[3][3] += a3 * bb.w;
        }
        __syncthreads();
    }
    float bt = beta[0];
    #pragma unroll
    for (int i = 0; i < 4; i++)
        #pragma unroll
        for (int j = 0; j < 4; j++)
            O[(size_t)(m0 + ty * 4 + i) * 1024 + n0 + tx * 4 + j] = bt * acc[i][j];
}

// ---------------- launch -----------------------------------------------------------
extern "C" void kernel_launch(void* const* d_in, const int* in_sizes, int n_in,
                              void* d_out, int out_size)
{
    const float* x      = (const float*)d_in[0];
    const float* x1     = (const float*)d_in[1];
    const float* x2     = (const float*)d_in[2];
    const float* w1     = (const float*)d_in[3];
    const float* b1     = (const float*)d_in[4];
    const float* w2     = (const float*)d_in[5];
    const float* b2     = (const float*)d_in[6];
    const float* gamma  = (const float*)d_in[7];
    const float* bnb    = (const float*)d_in[8];
    const float* beta   = (const float*)d_in[9];
    float* out = (float*)d_out;

    // conv1x1 for both inputs: grid (Ntiles=16, Mtiles=4, t*8+b=16)
    conv1x1_kernel<<<dim3(16, 4, 16), 256>>>(x1, x2, w1, b1);

    // conv3x3 + bias + lrelu + BN partials: grid (rowquad=8, co_tile=16, 16)
    conv3x3_kernel<<<dim3(8, 16, 16), 256>>>(w2, b2);

    // BN stats + apply
    bn_stats_kernel<<<4, 256>>>(gamma, bnb);
    bn_apply_kernel<<<(2 * 8 * 512 * 1024) / 256, 256>>>();

    // scores + softmax
    scores_kernel<<<dim3(8, 8, 8), 256>>>();
    softmax_kernel<<<4096, 256>>>();

    // attention output
    out_kernel<<<dim3(16, 8, 8), 256>>>(x, beta, out);
}